// round 14
// baseline (speedup 1.0000x reference)
#include <cuda_runtime.h>

#define BATCH 512
#define INF   512
#define OUTF  100
#define KD    5
#define OKC   500            // OUTF * KD
#define PLANE (OKC * BATCH)  // 256000
#define NZ    16             // split-K factor (K-slice = 32)
#define LOG2E 1.4426950408889634f

typedef unsigned long long u64;

// Split-K partials [z][c][b] (c = o*KD+k), and the reduced M, both *log2e.
__device__ __align__(16) float g_Mp[NZ][PLANE];
__device__ __align__(16) float g_M[PLANE];

// ---- packed f32x2 helpers (asm only) ----
__device__ __forceinline__ u64 f2add(u64 a, u64 b) {
    u64 r; asm("add.rn.f32x2 %0,%1,%2;" : "=l"(r) : "l"(a), "l"(b)); return r;
}
__device__ __forceinline__ u64 f2fma(u64 a, u64 b, u64 c) {
    u64 r; asm("fma.rn.f32x2 %0,%1,%2,%3;" : "=l"(r) : "l"(a), "l"(b), "l"(c)); return r;
}
__device__ __forceinline__ u64 pk(float lo, float hi) {
    u64 r; asm("mov.b64 %0,{%1,%2};" : "=l"(r) : "f"(lo), "f"(hi)); return r;
}
__device__ __forceinline__ void upk(u64 a, float& lo, float& hi) {
    asm("mov.b64 {%0,%1},%2;" : "=f"(lo), "=f"(hi) : "l"(a));
}
__device__ __forceinline__ u64 dup2(float v) { return pk(v, v); }
__device__ __forceinline__ float ex2_approx(float x) {
    float y; asm("ex2.approx.ftz.f32 %0, %1;" : "=f"(y) : "f"(x)); return y;
}
#define NEGABS_MASK 0x8000000080000000ULL   // OR -> -(|x|) on both halves

// ---------------------------------------------------------------------------
// Kernel 1: split-K GEMM, crossbar/fma-BALANCED tile.
// Block tile 64m x 128n, BK=16, K-slice 32 (2 k-tiles, double buffered),
// 256 threads, thread tile 4m(2 u64) x 8n. Per kk: 3 LDS.128 (12 crossbar cyc)
// feeding 16 FFMA2 (12 SM fma-cyc) -- balanced, vs 8-cyc-xbar/8-FFMA2 before.
// grid = (4 n, 8 m, 16 z) = 512 blocks.
// ---------------------------------------------------------------------------
__global__ void __launch_bounds__(256, 3)
gemm_kernel(const float* __restrict__ X, const float* __restrict__ W) {
    __shared__ __align__(16) float As[2][16][64];    // [buf][kk][m]   8 KB
    __shared__ __align__(16) float Bs[2][16][128];   // [buf][kk][n]  16 KB

    const int tid = threadIdx.x;
    const int tx  = tid & 15;          // 8 n each
    const int ty  = tid >> 4;          // 4 m each
    const int n0  = blockIdx.x * 128;
    const int m0  = blockIdx.y * 64;
    const int k0  = blockIdx.z * 32;

    // A loader: row ar (0..63), k quad kq (0/4/8/12); stores transposed.
    const int ar = tid & 63;
    const int kq = (tid >> 6) * 4;
    const float* xp = X + (m0 + ar) * INF + k0 + kq;

    // B loader: kk-row bkr (0..15), 8 cols at bcl (two float4); OKC % 4 == 0.
    const int bkr = tid >> 4;
    const int bcl = (tid & 15) * 8;
    const int bc  = n0 + bcl;
    const bool ok0 = bc < OKC;
    const bool ok1 = bc + 4 < OKC;
    const float* wp = W + (k0 + bkr) * OKC + bc;
    const float4 fz = make_float4(0.f, 0.f, 0.f, 0.f);

    // prologue: k-tile 0 -> buf 0
    float4 av  = *(const float4*)xp;
    float4 bv0 = ok0 ? *(const float4*)wp : fz;
    float4 bv1 = ok1 ? *(const float4*)(wp + 4) : fz;
    As[0][kq + 0][ar] = av.x;
    As[0][kq + 1][ar] = av.y;
    As[0][kq + 2][ar] = av.z;
    As[0][kq + 3][ar] = av.w;
    *(float4*)&Bs[0][bkr][bcl]     = bv0;
    *(float4*)&Bs[0][bkr][bcl + 4] = bv1;
    __syncthreads();

    u64 acc[2][8];                     // [m-pair][n]
    #pragma unroll
    for (int p = 0; p < 2; p++)
        #pragma unroll
        for (int j = 0; j < 8; j++) acc[p][j] = 0ULL;

    #pragma unroll
    for (int kt = 0; kt < 2; kt++) {
        if (kt == 0) {                 // prefetch k-tile 1 into registers
            av  = *(const float4*)(xp + 16);
            bv0 = ok0 ? *(const float4*)(wp + 16 * OKC) : fz;
            bv1 = ok1 ? *(const float4*)(wp + 16 * OKC + 4) : fz;
        }
        #pragma unroll
        for (int kk = 0; kk < 16; kk++) {
            ulonglong2 A = *(const ulonglong2*)&As[kt][kk][ty * 4];
            float4 b0 = *(const float4*)&Bs[kt][kk][tx * 8];
            float4 b1 = *(const float4*)&Bs[kt][kk][tx * 8 + 4];
            u64 d0 = pk(b0.x, b0.x);
            u64 d1 = pk(b0.y, b0.y);
            u64 d2 = pk(b0.z, b0.z);
            u64 d3 = pk(b0.w, b0.w);
            u64 d4 = pk(b1.x, b1.x);
            u64 d5 = pk(b1.y, b1.y);
            u64 d6 = pk(b1.z, b1.z);
            u64 d7 = pk(b1.w, b1.w);
            acc[0][0] = f2fma(A.x, d0, acc[0][0]);
            acc[1][0] = f2fma(A.y, d0, acc[1][0]);
            acc[0][1] = f2fma(A.x, d1, acc[0][1]);
            acc[1][1] = f2fma(A.y, d1, acc[1][1]);
            acc[0][2] = f2fma(A.x, d2, acc[0][2]);
            acc[1][2] = f2fma(A.y, d2, acc[1][2]);
            acc[0][3] = f2fma(A.x, d3, acc[0][3]);
            acc[1][3] = f2fma(A.y, d3, acc[1][3]);
            acc[0][4] = f2fma(A.x, d4, acc[0][4]);
            acc[1][4] = f2fma(A.y, d4, acc[1][4]);
            acc[0][5] = f2fma(A.x, d5, acc[0][5]);
            acc[1][5] = f2fma(A.y, d5, acc[1][5]);
            acc[0][6] = f2fma(A.x, d6, acc[0][6]);
            acc[1][6] = f2fma(A.y, d6, acc[1][6]);
            acc[0][7] = f2fma(A.x, d7, acc[0][7]);
            acc[1][7] = f2fma(A.y, d7, acc[1][7]);
        }
        if (kt == 0) {                 // stage k-tile 1 -> buf 1
            As[1][kq + 0][ar] = av.x;
            As[1][kq + 1][ar] = av.y;
            As[1][kq + 2][ar] = av.z;
            As[1][kq + 3][ar] = av.w;
            *(float4*)&Bs[1][bkr][bcl]     = bv0;
            *(float4*)&Bs[1][bkr][bcl + 4] = bv1;
            __syncthreads();
        }
    }

    // epilogue: store [c][b] scaled by log2e; 4 m values contiguous.
    float* plane = g_Mp[blockIdx.z];
    #pragma unroll
    for (int j = 0; j < 8; j++) {
        int c = n0 + tx * 8 + j;
        if (c < OKC) {
            float v0, v1, v2, v3;
            upk(acc[0][j], v0, v1);
            upk(acc[1][j], v2, v3);
            float4 o = make_float4(v0 * LOG2E, v1 * LOG2E, v2 * LOG2E, v3 * LOG2E);
            *(float4*)&plane[c * BATCH + m0 + ty * 4] = o;
        }
    }
}

// ---------------------------------------------------------------------------
// Kernel 1b: collapse the NZ split-K planes + zero `out` (replaces memset).
// ---------------------------------------------------------------------------
__global__ void __launch_bounds__(256)
reduce_kernel(float* __restrict__ out) {
    const int i = blockIdx.x * 256 + threadIdx.x;      // float4 index
    float4 s = ((const float4*)g_Mp[0])[i];
    #pragma unroll
    for (int z = 1; z < NZ; z++) {
        float4 t = ((const float4*)g_Mp[z])[i];
        s.x += t.x; s.y += t.y; s.z += t.z; s.w += t.w;
    }
    ((float4*)g_M)[i] = s;
    if (i < (BATCH * OUTF) / 4)
        ((float4*)out)[i] = make_float4(0.f, 0.f, 0.f, 0.f);
}

// ---------------------------------------------------------------------------
// Kernel 2: pairwise, uniform-i / register-j (unchanged; issue-bound ~73%).
// grid = (100, 8) = 800 blocks x 256 thr; thread owns j = tid, tid+256.
// ---------------------------------------------------------------------------
__global__ void __launch_bounds__(256)
pairwise_kernel(float* __restrict__ out) {
    const int o  = blockIdx.x;
    const int z  = blockIdx.y;
    const int i0 = z * 64;
    const int tid = threadIdx.x;
    const int j1 = tid, j2 = tid + 256;

    __shared__ __align__(16) float sP[32][12];   // pair q: (M[2q,k],M[2q+1,k]), pad

    const float* base = g_M + o * KD * BATCH;

    #pragma unroll
    for (int idx = tid; idx < 64 * KD; idx += 256) {
        int k = idx >> 6, b = idx & 63;
        sP[b >> 1][2 * k + (b & 1)] = base[k * BATCH + i0 + b];
    }

    u64 nm1[KD], nm2[KD];
    #pragma unroll
    for (int k = 0; k < KD; k++) {
        nm1[k] = dup2(-base[k * BATCH + j1]);
        nm2[k] = dup2(-base[k * BATCH + j2]);
    }
    __syncthreads();

    float acc1a = 0.f, acc1b = 0.f, acc2a = 0.f, acc2b = 0.f;

    #pragma unroll 8
    for (int s = 0; s < 32; s++) {
        const float* row = &sP[s][0];
        ulonglong2 q01 = *(const ulonglong2*)(row);
        ulonglong2 q23 = *(const ulonglong2*)(row + 4);
        u64 p4 = *(const u64*)(row + 8);
        {
            u64 d0 = f2add(q01.x, nm1[0]) | NEGABS_MASK;
            u64 d1 = f2add(q01.y, nm1[1]) | NEGABS_MASK;
            u64 d2 = f2add(q23.x, nm1[2]) | NEGABS_MASK;
            u64 d3 = f2add(q23.y, nm1[3]) | NEGABS_MASK;
            u64 d4 = f2add(p4,    nm1[4]) | NEGABS_MASK;
            u64 t = f2add(f2add(f2add(d0, d1), f2add(d2, d3)), d4);
            float tf0, tf1; upk(t, tf0, tf1);
            acc1a += ex2_approx(tf0);
            acc1b += ex2_approx(tf1);
        }
        {
            u64 d0 = f2add(q01.x, nm2[0]) | NEGABS_MASK;
            u64 d1 = f2add(q01.y, nm2[1]) | NEGABS_MASK;
            u64 d2 = f2add(q23.x, nm2[2]) | NEGABS_MASK;
            u64 d3 = f2add(q23.y, nm2[3]) | NEGABS_MASK;
            u64 d4 = f2add(p4,    nm2[4]) | NEGABS_MASK;
            u64 t = f2add(f2add(f2add(d0, d1), f2add(d2, d3)), d4);
            float tf0, tf1; upk(t, tf0, tf1);
            acc2a += ex2_approx(tf0);
            acc2b += ex2_approx(tf1);
        }
    }

    float r1 = acc1a + acc1b;
    float r2 = acc2a + acc2b;
    if ((j1 >> 6) == z) r1 -= 1.0f;   // self term exp2(-0) = 1
    if ((j2 >> 6) == z) r2 -= 1.0f;
    atomicAdd(&out[j1 * OUTF + o], r1);
    atomicAdd(&out[j2 * OUTF + o], r2);
}

// ---------------------------------------------------------------------------
extern "C" void kernel_launch(void* const* d_in, const int* in_sizes, int n_in,
                              void* d_out, int out_size) {
    const float* x = (const float*)d_in[0];   // [512, 512]
    const float* T = (const float*)d_in[1];   // [512, 100, 5] == [512, 500]
    float* out = (float*)d_out;               // [512, 100]

    dim3 ggrid(4, 8, NZ);                     // 512 blocks
    gemm_kernel<<<ggrid, 256>>>(x, T);

    reduce_kernel<<<PLANE / 4 / 256, 256>>>(out);   // 250 blocks, also zeros out

    dim3 pgrid(OUTF, 8);                      // 800 blocks
    pairwise_kernel<<<pgrid, 256>>>(out);
}

// round 15
// speedup vs baseline: 1.0069x; 1.0069x over previous
#include <cuda_runtime.h>

#define BATCH 512
#define INF   512
#define OUTF  100
#define KD    5
#define OKC   500            // OUTF * KD
#define PLANE (OKC * BATCH)  // 256000
#define NZ    16             // split-K factor (K-slice = 32)
#define LOG2E 1.4426950408889634f

typedef unsigned long long u64;

// Split-K partials [z][c][b] (c = o*KD+k), and the reduced M, both *log2e.
__device__ __align__(16) float g_Mp[NZ][PLANE];
__device__ __align__(16) float g_M[PLANE];

// ---- packed f32x2 helpers (asm only) ----
__device__ __forceinline__ u64 f2add(u64 a, u64 b) {
    u64 r; asm("add.rn.f32x2 %0,%1,%2;" : "=l"(r) : "l"(a), "l"(b)); return r;
}
__device__ __forceinline__ u64 f2fma(u64 a, u64 b, u64 c) {
    u64 r; asm("fma.rn.f32x2 %0,%1,%2,%3;" : "=l"(r) : "l"(a), "l"(b), "l"(c)); return r;
}
__device__ __forceinline__ u64 pk(float lo, float hi) {
    u64 r; asm("mov.b64 %0,{%1,%2};" : "=l"(r) : "f"(lo), "f"(hi)); return r;
}
__device__ __forceinline__ void upk(u64 a, float& lo, float& hi) {
    asm("mov.b64 {%0,%1},%2;" : "=f"(lo), "=f"(hi) : "l"(a));
}
__device__ __forceinline__ u64 dup2(float v) { return pk(v, v); }
__device__ __forceinline__ float ex2_approx(float x) {
    float y; asm("ex2.approx.ftz.f32 %0, %1;" : "=f"(y) : "f"(x)); return y;
}
#define NEGABS_MASK 0x8000000080000000ULL   // OR -> -(|x|) on both halves

// ---------------------------------------------------------------------------
// Kernel 1: split-K GEMM, crossbar/fma-BALANCED tile.
// Block tile 64m x 128n, BK=16, K-slice 32 (2 k-tiles, double buffered),
// 256 threads, thread tile 4m(2 u64) x 8n. Per kk: 3 LDS.128 (12 crossbar cyc)
// feeding 16 FFMA2 (12 SM fma-cyc) -- balanced, vs 8-cyc-xbar/8-FFMA2 before.
// grid = (4 n, 8 m, 16 z) = 512 blocks.
// ---------------------------------------------------------------------------
__global__ void __launch_bounds__(256, 3)
gemm_kernel(const float* __restrict__ X, const float* __restrict__ W) {
    __shared__ __align__(16) float As[2][16][64];    // [buf][kk][m]   8 KB
    __shared__ __align__(16) float Bs[2][16][128];   // [buf][kk][n]  16 KB

    const int tid = threadIdx.x;
    const int tx  = tid & 15;          // 8 n each
    const int ty  = tid >> 4;          // 4 m each
    const int n0  = blockIdx.x * 128;
    const int m0  = blockIdx.y * 64;
    const int k0  = blockIdx.z * 32;

    // A loader: row ar (0..63), k quad kq (0/4/8/12); stores transposed.
    const int ar = tid & 63;
    const int kq = (tid >> 6) * 4;
    const float* xp = X + (m0 + ar) * INF + k0 + kq;

    // B loader: kk-row bkr (0..15), 8 cols at bcl (two float4); OKC % 4 == 0.
    const int bkr = tid >> 4;
    const int bcl = (tid & 15) * 8;
    const int bc  = n0 + bcl;
    const bool ok0 = bc < OKC;
    const bool ok1 = bc + 4 < OKC;
    const float* wp = W + (k0 + bkr) * OKC + bc;
    const float4 fz = make_float4(0.f, 0.f, 0.f, 0.f);

    // prologue: k-tile 0 -> buf 0
    float4 av  = *(const float4*)xp;
    float4 bv0 = ok0 ? *(const float4*)wp : fz;
    float4 bv1 = ok1 ? *(const float4*)(wp + 4) : fz;
    As[0][kq + 0][ar] = av.x;
    As[0][kq + 1][ar] = av.y;
    As[0][kq + 2][ar] = av.z;
    As[0][kq + 3][ar] = av.w;
    *(float4*)&Bs[0][bkr][bcl]     = bv0;
    *(float4*)&Bs[0][bkr][bcl + 4] = bv1;
    __syncthreads();

    u64 acc[2][8];                     // [m-pair][n]
    #pragma unroll
    for (int p = 0; p < 2; p++)
        #pragma unroll
        for (int j = 0; j < 8; j++) acc[p][j] = 0ULL;

    #pragma unroll
    for (int kt = 0; kt < 2; kt++) {
        if (kt == 0) {                 // prefetch k-tile 1 into registers
            av  = *(const float4*)(xp + 16);
            bv0 = ok0 ? *(const float4*)(wp + 16 * OKC) : fz;
            bv1 = ok1 ? *(const float4*)(wp + 16 * OKC + 4) : fz;
        }
        #pragma unroll
        for (int kk = 0; kk < 16; kk++) {
            ulonglong2 A = *(const ulonglong2*)&As[kt][kk][ty * 4];
            float4 b0 = *(const float4*)&Bs[kt][kk][tx * 8];
            float4 b1 = *(const float4*)&Bs[kt][kk][tx * 8 + 4];
            u64 d0 = pk(b0.x, b0.x);
            u64 d1 = pk(b0.y, b0.y);
            u64 d2 = pk(b0.z, b0.z);
            u64 d3 = pk(b0.w, b0.w);
            u64 d4 = pk(b1.x, b1.x);
            u64 d5 = pk(b1.y, b1.y);
            u64 d6 = pk(b1.z, b1.z);
            u64 d7 = pk(b1.w, b1.w);
            acc[0][0] = f2fma(A.x, d0, acc[0][0]);
            acc[1][0] = f2fma(A.y, d0, acc[1][0]);
            acc[0][1] = f2fma(A.x, d1, acc[0][1]);
            acc[1][1] = f2fma(A.y, d1, acc[1][1]);
            acc[0][2] = f2fma(A.x, d2, acc[0][2]);
            acc[1][2] = f2fma(A.y, d2, acc[1][2]);
            acc[0][3] = f2fma(A.x, d3, acc[0][3]);
            acc[1][3] = f2fma(A.y, d3, acc[1][3]);
            acc[0][4] = f2fma(A.x, d4, acc[0][4]);
            acc[1][4] = f2fma(A.y, d4, acc[1][4]);
            acc[0][5] = f2fma(A.x, d5, acc[0][5]);
            acc[1][5] = f2fma(A.y, d5, acc[1][5]);
            acc[0][6] = f2fma(A.x, d6, acc[0][6]);
            acc[1][6] = f2fma(A.y, d6, acc[1][6]);
            acc[0][7] = f2fma(A.x, d7, acc[0][7]);
            acc[1][7] = f2fma(A.y, d7, acc[1][7]);
        }
        if (kt == 0) {                 // stage k-tile 1 -> buf 1
            As[1][kq + 0][ar] = av.x;
            As[1][kq + 1][ar] = av.y;
            As[1][kq + 2][ar] = av.z;
            As[1][kq + 3][ar] = av.w;
            *(float4*)&Bs[1][bkr][bcl]     = bv0;
            *(float4*)&Bs[1][bkr][bcl + 4] = bv1;
            __syncthreads();
        }
    }

    // epilogue: store [c][b] scaled by log2e; 4 m values contiguous.
    float* plane = g_Mp[blockIdx.z];
    #pragma unroll
    for (int j = 0; j < 8; j++) {
        int c = n0 + tx * 8 + j;
        if (c < OKC) {
            float v0, v1, v2, v3;
            upk(acc[0][j], v0, v1);
            upk(acc[1][j], v2, v3);
            float4 o = make_float4(v0 * LOG2E, v1 * LOG2E, v2 * LOG2E, v3 * LOG2E);
            *(float4*)&plane[c * BATCH + m0 + ty * 4] = o;
        }
    }
}

// ---------------------------------------------------------------------------
// Kernel 1b: collapse the NZ split-K planes + zero `out` (replaces memset).
// ---------------------------------------------------------------------------
__global__ void __launch_bounds__(256)
reduce_kernel(float* __restrict__ out) {
    const int i = blockIdx.x * 256 + threadIdx.x;      // float4 index
    float4 s = ((const float4*)g_Mp[0])[i];
    #pragma unroll
    for (int z = 1; z < NZ; z++) {
        float4 t = ((const float4*)g_Mp[z])[i];
        s.x += t.x; s.y += t.y; s.z += t.z; s.w += t.w;
    }
    ((float4*)g_M)[i] = s;
    if (i < (BATCH * OUTF) / 4)
        ((float4*)out)[i] = make_float4(0.f, 0.f, 0.f, 0.f);
}

// ---------------------------------------------------------------------------
// Kernel 2: pairwise, uniform-i / register-j (unchanged; issue-bound ~73%).
// grid = (100, 8) = 800 blocks x 256 thr; thread owns j = tid, tid+256.
// ---------------------------------------------------------------------------
__global__ void __launch_bounds__(256)
pairwise_kernel(float* __restrict__ out) {
    const int o  = blockIdx.x;
    const int z  = blockIdx.y;
    const int i0 = z * 64;
    const int tid = threadIdx.x;
    const int j1 = tid, j2 = tid + 256;

    __shared__ __align__(16) float sP[32][12];   // pair q: (M[2q,k],M[2q+1,k]), pad

    const float* base = g_M + o * KD * BATCH;

    #pragma unroll
    for (int idx = tid; idx < 64 * KD; idx += 256) {
        int k = idx >> 6, b = idx & 63;
        sP[b >> 1][2 * k + (b & 1)] = base[k * BATCH + i0 + b];
    }

    u64 nm1[KD], nm2[KD];
    #pragma unroll
    for (int k = 0; k < KD; k++) {
        nm1[k] = dup2(-base[k * BATCH + j1]);
        nm2[k] = dup2(-base[k * BATCH + j2]);
    }
    __syncthreads();

    float acc1a = 0.f, acc1b = 0.f, acc2a = 0.f, acc2b = 0.f;

    #pragma unroll 8
    for (int s = 0; s < 32; s++) {
        const float* row = &sP[s][0];
        ulonglong2 q01 = *(const ulonglong2*)(row);
        ulonglong2 q23 = *(const ulonglong2*)(row + 4);
        u64 p4 = *(const u64*)(row + 8);
        {
            u64 d0 = f2add(q01.x, nm1[0]) | NEGABS_MASK;
            u64 d1 = f2add(q01.y, nm1[1]) | NEGABS_MASK;
            u64 d2 = f2add(q23.x, nm1[2]) | NEGABS_MASK;
            u64 d3 = f2add(q23.y, nm1[3]) | NEGABS_MASK;
            u64 d4 = f2add(p4,    nm1[4]) | NEGABS_MASK;
            u64 t = f2add(f2add(f2add(d0, d1), f2add(d2, d3)), d4);
            float tf0, tf1; upk(t, tf0, tf1);
            acc1a += ex2_approx(tf0);
            acc1b += ex2_approx(tf1);
        }
        {
            u64 d0 = f2add(q01.x, nm2[0]) | NEGABS_MASK;
            u64 d1 = f2add(q01.y, nm2[1]) | NEGABS_MASK;
            u64 d2 = f2add(q23.x, nm2[2]) | NEGABS_MASK;
            u64 d3 = f2add(q23.y, nm2[3]) | NEGABS_MASK;
            u64 d4 = f2add(p4,    nm2[4]) | NEGABS_MASK;
            u64 t = f2add(f2add(f2add(d0, d1), f2add(d2, d3)), d4);
            float tf0, tf1; upk(t, tf0, tf1);
            acc2a += ex2_approx(tf0);
            acc2b += ex2_approx(tf1);
        }
    }

    float r1 = acc1a + acc1b;
    float r2 = acc2a + acc2b;
    if ((j1 >> 6) == z) r1 -= 1.0f;   // self term exp2(-0) = 1
    if ((j2 >> 6) == z) r2 -= 1.0f;
    atomicAdd(&out[j1 * OUTF + o], r1);
    atomicAdd(&out[j2 * OUTF + o], r2);
}

// ---------------------------------------------------------------------------
extern "C" void kernel_launch(void* const* d_in, const int* in_sizes, int n_in,
                              void* d_out, int out_size) {
    const float* x = (const float*)d_in[0];   // [512, 512]
    const float* T = (const float*)d_in[1];   // [512, 100, 5] == [512, 500]
    float* out = (float*)d_out;               // [512, 100]

    dim3 ggrid(4, 8, NZ);                     // 512 blocks
    gemm_kernel<<<ggrid, 256>>>(x, T);

    reduce_kernel<<<PLANE / 4 / 256, 256>>>(out);   // 250 blocks, also zeros out

    dim3 pgrid(OUTF, 8);                      // 800 blocks
    pairwise_kernel<<<pgrid, 256>>>(out);
}